// round 1
// baseline (speedup 1.0000x reference)
#include <cuda_runtime.h>
#include <math.h>

#define BB 4
#define NN 128
#define FF 128
#define SS 5
#define TGLOB 32
#define LL 2
#define TBL 2048
#define LMAX 16.0f
#define TBL_SCALE (TBL / LMAX)   /* 128.0f */

// ---------------- persistent scratch (device globals; no allocation) ------
__device__ float g_pos[BB * NN * 3];
__device__ float g_scal[BB * NN * FF];
__device__ float g_vec[BB * NN * 3 * FF];   // [b][n][d][c]
__device__ float g_z[BB * NN * FF];
__device__ float g_A4[BB * NN * 4 * FF];    // gated A for k=0..3 only
__device__ float g_tbl[LL * TBL * 512];     // radial MLP table, [layer][t][c*4+j]

// ---------------- table build: Rw(lng) = silu(lng*Wr1+br1) @ Wr2 ----------
__global__ __launch_bounds__(128) void k_tables(const float* __restrict__ Wr1,
                                                const float* __restrict__ br1,
                                                const float* __restrict__ Wr2) {
    int t = blockIdx.x, i = blockIdx.y, c = threadIdx.x;
    float lng = (float)t * (LMAX / (float)TBL);
    __shared__ float h[64];
    if (c < 64) {
        float p = lng * Wr1[i * 64 + c] + br1[i * 64 + c];
        h[c] = p / (1.0f + expf(-p));
    }
    __syncthreads();
    const float* W = Wr2 + i * 64 * 512;
    float a0 = 0.f, a1 = 0.f, a2 = 0.f, a3 = 0.f;
#pragma unroll 8
    for (int m = 0; m < 64; m++) {
        float hm = h[m];
        const float* Wm = W + m * 512 + c;
        a0 = fmaf(hm, Wm[0],   a0);
        a1 = fmaf(hm, Wm[128], a1);
        a2 = fmaf(hm, Wm[256], a2);
        a3 = fmaf(hm, Wm[384], a3);
    }
    float* dst = g_tbl + ((size_t)i * TBL + t) * 512 + c * 4;
    dst[0] = a0; dst[1] = a1; dst[2] = a2; dst[3] = a3;
}

// ---------------- init: embed scalars, zero vectors, copy positions -------
__global__ __launch_bounds__(128) void k_init(const float* __restrict__ positions,
                                              const int* __restrict__ node_features,
                                              const float* __restrict__ gf,
                                              const float* __restrict__ W_embed,
                                              const float* __restrict__ b_embed) {
    int bn = blockIdx.x;           // b*NN + n
    int b = bn / NN;
    int c = threadIdx.x;
    int nf = node_features[bn];    // 1..SS
    float s = W_embed[(nf - 1) * FF + c] + b_embed[c];
#pragma unroll 8
    for (int t = 0; t < TGLOB; t++)
        s = fmaf(gf[b * TGLOB + t], W_embed[(SS + t) * FF + c], s);
    g_scal[bn * FF + c] = s;
    g_vec[bn * 3 * FF + 0 * FF + c] = 0.f;
    g_vec[bn * 3 * FF + 1 * FF + c] = 0.f;
    g_vec[bn * 3 * FF + 2 * FF + c] = 0.f;
    if (c < 3) g_pos[bn * 3 + c] = positions[bn * 3 + c];
}

// ---------------- z = scal @ Wnode[layer] ----------------------------------
__global__ __launch_bounds__(128) void k_z(const float* __restrict__ Wnode, int layer) {
    int bn = blockIdx.x;
    int c = threadIdx.x;
    __shared__ float srow[FF];
    srow[c] = g_scal[bn * FF + c];
    __syncthreads();
    const float* W = Wnode + layer * FF * FF;
    float acc = 0.f;
#pragma unroll 8
    for (int k = 0; k < FF; k++)
        acc = fmaf(srow[k], W[k * FF + c], acc);
    g_z[bn * FF + c] = acc;
}

// ---------------- message gather + symmetric-contraction gate -------------
__global__ __launch_bounds__(128) void k_msg(const float* __restrict__ pos_in,
                                             const float* __restrict__ c1w,
                                             const float* __restrict__ c2w,
                                             const float* __restrict__ c3w,
                                             int layer) {
    const int r = blockIdx.x;
    const int b = blockIdx.y;
    const int c = threadIdx.x;

    __shared__ float sp[NN * 3];
    __shared__ float sp0[NN * 3];
    for (int idx = c; idx < NN * 3; idx += 128) {
        sp[idx]  = g_pos[b * NN * 3 + idx];
        sp0[idx] = pos_in[b * NN * 3 + idx];
    }
    __syncthreads();

    const float rx = sp[r * 3 + 0], ry = sp[r * 3 + 1], rz = sp[r * 3 + 2];
    const float r0x = sp0[r * 3 + 0], r0y = sp0[r * 3 + 1], r0z = sp0[r * 3 + 2];

    const float s3 = 1.7320508075688772f, s5 = 2.2360679774997896f,
                s15 = 3.872983346207417f, s35_8 = 2.091650066335189f,
                s105 = 10.246950765959598f, s21_8 = 1.6201851746019651f,
                s7 = 2.6457513110645907f;

    float A[16];
#pragma unroll
    for (int k = 0; k < 16; k++) A[k] = 0.f;

    const float* tb = g_tbl + (size_t)layer * TBL * 512;
    const float* zbase = g_z + b * NN * FF;
    const float* vbase = g_vec + b * NN * 3 * FF;

    for (int s = 0; s < NN; s++) {
        if (s == r) continue;
        // envelope from ORIGINAL positions (lengths_0)
        float dx0 = r0x - sp0[s * 3 + 0];
        float dy0 = r0y - sp0[s * 3 + 1];
        float dz0 = r0z - sp0[s * 3 + 2];
        float l0 = sqrtf(dx0 * dx0 + dy0 * dy0 + dz0 * dz0 + 1e-12f);
        float env = (l0 < 10.0f) ? 0.5f * (cosf(l0 * 0.3141592653589793f) + 1.0f) : 0.0f;
        if (env == 0.0f) continue;

        float vx = rx - sp[s * 3 + 0];
        float vy = ry - sp[s * 3 + 1];
        float vz = rz - sp[s * 3 + 2];
        float lng = sqrtf(vx * vx + vy * vy + vz * vz + 1e-12f);
        float inv = 1.0f / lng;
        float ux = vx * inv, uy = vy * inv, uz = vz * inv;

        // spherical harmonics (l<=3)
        float xx = ux * ux, yy = uy * uy, zz = uz * uz;
        float Y1 = s3 * ux, Y2 = s3 * uy, Y3 = s3 * uz;
        float Y4 = s15 * ux * uy, Y5 = s15 * uy * uz;
        float Y6 = 0.5f * s5 * (3.f * zz - 1.f);
        float Y7 = s15 * ux * uz;
        float Y8 = 0.5f * s15 * (xx - yy);
        float Y9 = s35_8 * uy * (3.f * xx - yy);
        float Y10 = s105 * ux * uy * uz;
        float Y11 = s21_8 * uy * (5.f * zz - 1.f);
        float Y12 = 0.5f * s7 * uz * (5.f * zz - 3.f);
        float Y13 = s21_8 * ux * (5.f * zz - 1.f);
        float Y14 = 0.5f * s105 * uz * (xx - yy);
        float Y15 = s35_8 * ux * (xx - 3.f * yy);

        // radial weights via table lookup + lerp
        float tp = fminf(lng * TBL_SCALE, (float)TBL - 1.001f);
        int it = (int)tp;
        float fr = tp - (float)it;
        const float4 w0 = *(const float4*)(tb + (size_t)it * 512 + (c << 2));
        const float4 w1 = *(const float4*)(tb + (size_t)(it + 1) * 512 + (c << 2));
        float Rw0 = (w0.x + fr * (w1.x - w0.x)) * env;
        float Rw1 = (w0.y + fr * (w1.y - w0.y)) * env;
        float Rw2 = (w0.z + fr * (w1.z - w0.z)) * env;
        float Rw3 = (w0.w + fr * (w1.w - w0.w)) * env;

        // f = z[s] + vec[s] . u
        const float* vrow = vbase + s * 3 * FF;
        float f = zbase[s * FF + c];
        f = fmaf(vrow[c], ux, f);
        f = fmaf(vrow[FF + c], uy, f);
        f = fmaf(vrow[2 * FF + c], uz, f);

        float t0 = Rw0 * f, t1 = Rw1 * f, t2 = Rw2 * f, t3 = Rw3 * f;
        A[0] += t0;
        A[1]  = fmaf(t1, Y1,  A[1]);
        A[2]  = fmaf(t1, Y2,  A[2]);
        A[3]  = fmaf(t1, Y3,  A[3]);
        A[4]  = fmaf(t2, Y4,  A[4]);
        A[5]  = fmaf(t2, Y5,  A[5]);
        A[6]  = fmaf(t2, Y6,  A[6]);
        A[7]  = fmaf(t2, Y7,  A[7]);
        A[8]  = fmaf(t2, Y8,  A[8]);
        A[9]  = fmaf(t3, Y9,  A[9]);
        A[10] = fmaf(t3, Y10, A[10]);
        A[11] = fmaf(t3, Y11, A[11]);
        A[12] = fmaf(t3, Y12, A[12]);
        A[13] = fmaf(t3, Y13, A[13]);
        A[14] = fmaf(t3, Y14, A[14]);
        A[15] = fmaf(t3, Y15, A[15]);
    }

    const float invavg = 1.0f / 16.0f;
#pragma unroll
    for (int k = 0; k < 16; k++) A[k] *= invavg;

    // per-ell invariants
    float n0 = A[0] * A[0];
    float n1 = A[1] * A[1] + A[2] * A[2] + A[3] * A[3];
    float n2 = A[4] * A[4] + A[5] * A[5] + A[6] * A[6] + A[7] * A[7] + A[8] * A[8];
    float n3 = 0.f;
#pragma unroll
    for (int k = 9; k < 16; k++) n3 = fmaf(A[k], A[k], n3);

    const int co = (layer * 4) * FF + c;
    float g0 = 1.f + c1w[co]          * n0 + c2w[co]          * n0 * n0 + c3w[co]          * n0 * n0 * n0;
    float g1 = 1.f + c1w[co + FF]     * n1 + c2w[co + FF]     * n1 * n1 + c3w[co + FF]     * n1 * n1 * n1;

    float* dst = g_A4 + ((size_t)(b * NN + r)) * 4 * FF;
    dst[c]          = A[0] * g0;
    dst[FF + c]     = A[1] * g1;
    dst[2 * FF + c] = A[2] * g1;
    dst[3 * FF + c] = A[3] * g1;
}

// ---------------- node update: mix, gate, equivariant position update -----
__global__ __launch_bounds__(128) void k_node(const float* __restrict__ Wmix0,
                                              const float* __restrict__ Wmix1,
                                              const float* __restrict__ Wg1,
                                              const float* __restrict__ Wg2,
                                              const float* __restrict__ Wvout,
                                              int layer) {
    int bn = blockIdx.x;
    int c = threadIdx.x;
    __shared__ float sA[4 * FF];
    __shared__ float sscal[FF];
    __shared__ float sh[16];
    __shared__ float rb[3][4];

    const float* asrc = g_A4 + (size_t)bn * 4 * FF;
#pragma unroll
    for (int k = 0; k < 4; k++) sA[k * FF + c] = asrc[k * FF + c];
    __syncthreads();

    const float* M0 = Wmix0 + layer * FF * FF;
    const float* M1 = Wmix1 + layer * FF * FF;
    float sc = 0.f, v0 = 0.f, v1 = 0.f, v2 = 0.f;
#pragma unroll 4
    for (int k = 0; k < FF; k++) {
        float m0 = M0[k * FF + c];
        float m1 = M1[k * FF + c];
        sc = fmaf(sA[k],          m0, sc);
        v0 = fmaf(sA[FF + k],     m1, v0);
        v1 = fmaf(sA[2 * FF + k], m1, v1);
        v2 = fmaf(sA[3 * FF + k], m1, v2);
    }
    sscal[c] = sc;
    __syncthreads();

    if (c < 16) {
        const float* G1 = Wg1 + layer * FF * 16;
        float a = 0.f;
#pragma unroll 8
        for (int k = 0; k < FF; k++) a = fmaf(sscal[k], G1[k * 16 + c], a);
        sh[c] = a / (1.0f + expf(-a));
    }
    __syncthreads();

    const float* G2 = Wg2 + layer * 16 * FF;
    float gate = 0.f;
#pragma unroll
    for (int j = 0; j < 16; j++) gate = fmaf(sh[j], G2[j * FF + c], gate);
    float w = gate * Wvout[layer * FF + c];

    float m0 = v0 * w, m1 = v1 * w, m2 = v2 * w;
#pragma unroll
    for (int off = 16; off > 0; off >>= 1) {
        m0 += __shfl_down_sync(0xffffffffu, m0, off);
        m1 += __shfl_down_sync(0xffffffffu, m1, off);
        m2 += __shfl_down_sync(0xffffffffu, m2, off);
    }
    if ((c & 31) == 0) {
        int wp = c >> 5;
        rb[0][wp] = m0; rb[1][wp] = m1; rb[2][wp] = m2;
    }
    __syncthreads();
    if (c < 3) {
        float acc = rb[c][0] + rb[c][1] + rb[c][2] + rb[c][3];
        g_pos[bn * 3 + c] += acc;
    }

    g_scal[bn * FF + c] = sc;
    g_vec[bn * 3 * FF + c] = v0;
    g_vec[bn * 3 * FF + FF + c] = v1;
    g_vec[bn * 3 * FF + 2 * FF + c] = v2;
}

// ---------------- output: pos - pos0 ---------------------------------------
__global__ void k_out(const float* __restrict__ pos_in, float* __restrict__ out) {
    int i = blockIdx.x * blockDim.x + threadIdx.x;
    if (i < BB * NN * 3) out[i] = g_pos[i] - pos_in[i];
}

// ---------------------------------------------------------------------------
extern "C" void kernel_launch(void* const* d_in, const int* in_sizes, int n_in,
                              void* d_out, int out_size) {
    const float* positions     = (const float*)d_in[0];
    const int*   node_features = (const int*)d_in[1];
    const float* gf            = (const float*)d_in[2];
    const float* W_embed       = (const float*)d_in[3];
    const float* b_embed       = (const float*)d_in[4];
    const float* Wr1           = (const float*)d_in[5];
    const float* br1           = (const float*)d_in[6];
    const float* Wr2           = (const float*)d_in[7];
    const float* Wnode         = (const float*)d_in[8];
    const float* c1w           = (const float*)d_in[9];
    const float* c2w           = (const float*)d_in[10];
    const float* c3w           = (const float*)d_in[11];
    const float* Wmix0         = (const float*)d_in[12];
    const float* Wmix1         = (const float*)d_in[13];
    const float* Wg1           = (const float*)d_in[14];
    const float* Wg2           = (const float*)d_in[15];
    const float* Wvout         = (const float*)d_in[16];
    float* out = (float*)d_out;

    k_tables<<<dim3(TBL, LL), 128>>>(Wr1, br1, Wr2);
    k_init<<<BB * NN, 128>>>(positions, node_features, gf, W_embed, b_embed);
    for (int i = 0; i < LL; i++) {
        k_z<<<BB * NN, 128>>>(Wnode, i);
        k_msg<<<dim3(NN, BB), 128>>>(positions, c1w, c2w, c3w, i);
        k_node<<<BB * NN, 128>>>(Wmix0, Wmix1, Wg1, Wg2, Wvout, i);
    }
    k_out<<<(BB * NN * 3 + 127) / 128, 128>>>(positions, out);
}

// round 2
// speedup vs baseline: 1.2416x; 1.2416x over previous
#include <cuda_runtime.h>
#include <math.h>

#define BB 4
#define NN 128
#define FF 128
#define SS 5
#define TGLOB 32
#define LL 2
#define TBL 2048
#define LMAX 16.0f
#define TBL_SCALE (TBL / LMAX)   /* 128.0f */

// ---------------- persistent scratch (device globals; no allocation) ------
__device__ float g_pos[BB * NN * 3];
__device__ float g_scal[BB * NN * FF];
__device__ float g_vec[BB * NN * 3 * FF];   // [b][n][d][c]
__device__ float g_z[BB * NN * FF];
__device__ float g_A4[BB * NN * 4 * FF];    // gated A for k=0..3 only
__device__ float g_tbl[LL * TBL * 512];     // radial MLP table, [layer][t][c*4+j]

// ---------------- table build: Rw(lng) = silu(lng*Wr1+br1) @ Wr2 ----------
__global__ __launch_bounds__(128) void k_tables(const float* __restrict__ Wr1,
                                                const float* __restrict__ br1,
                                                const float* __restrict__ Wr2) {
    int t = blockIdx.x, i = blockIdx.y, c = threadIdx.x;
    float lng = (float)t * (LMAX / (float)TBL);
    __shared__ float h[64];
    if (c < 64) {
        float p = lng * Wr1[i * 64 + c] + br1[i * 64 + c];
        h[c] = p / (1.0f + expf(-p));
    }
    __syncthreads();
    const float* W = Wr2 + i * 64 * 512;
    float a0 = 0.f, a1 = 0.f, a2 = 0.f, a3 = 0.f;
#pragma unroll 8
    for (int m = 0; m < 64; m++) {
        float hm = h[m];
        const float* Wm = W + m * 512 + c;
        a0 = fmaf(hm, Wm[0],   a0);
        a1 = fmaf(hm, Wm[128], a1);
        a2 = fmaf(hm, Wm[256], a2);
        a3 = fmaf(hm, Wm[384], a3);
    }
    float* dst = g_tbl + ((size_t)i * TBL + t) * 512 + c * 4;
    dst[0] = a0; dst[1] = a1; dst[2] = a2; dst[3] = a3;
}

// ---------------- init: embed scalars, zero vectors, z(layer0) ------------
__global__ __launch_bounds__(128) void k_init(const float* __restrict__ positions,
                                              const int* __restrict__ node_features,
                                              const float* __restrict__ gf,
                                              const float* __restrict__ W_embed,
                                              const float* __restrict__ b_embed,
                                              const float* __restrict__ Wnode) {
    int bn = blockIdx.x;           // b*NN + n
    int b = bn / NN;
    int c = threadIdx.x;
    int nf = node_features[bn];    // 1..SS
    float s = W_embed[(nf - 1) * FF + c] + b_embed[c];
#pragma unroll 8
    for (int t = 0; t < TGLOB; t++)
        s = fmaf(gf[b * TGLOB + t], W_embed[(SS + t) * FF + c], s);
    g_scal[bn * FF + c] = s;
    g_vec[bn * 3 * FF + 0 * FF + c] = 0.f;
    g_vec[bn * 3 * FF + 1 * FF + c] = 0.f;
    g_vec[bn * 3 * FF + 2 * FF + c] = 0.f;
    if (c < 3) g_pos[bn * 3 + c] = positions[bn * 3 + c];

    // fused z for layer 0: z = scal @ Wnode[0]
    __shared__ float srow[FF];
    srow[c] = s;
    __syncthreads();
    float acc = 0.f;
#pragma unroll 8
    for (int k = 0; k < FF; k++)
        acc = fmaf(srow[k], Wnode[k * FF + c], acc);
    g_z[bn * FF + c] = acc;
}

// ---------------- message gather + symmetric-contraction gate -------------
// blockDim = (128, 4): c = channel, q = sender-group (senders q, q+4, ...)
__global__ __launch_bounds__(512) void k_msg(const float* __restrict__ pos_in,
                                             const float* __restrict__ c1w,
                                             const float* __restrict__ c2w,
                                             const float* __restrict__ c3w,
                                             int layer) {
    const int r = blockIdx.x;
    const int b = blockIdx.y;
    const int c = threadIdx.x;
    const int q = threadIdx.y;
    const int tid = q * 128 + c;

    __shared__ float sp[NN * 3];
    __shared__ float sp0[NN * 3];
    __shared__ float red[3][16 * FF];
    for (int idx = tid; idx < NN * 3; idx += 512) {
        sp[idx]  = g_pos[b * NN * 3 + idx];
        sp0[idx] = pos_in[b * NN * 3 + idx];
    }
    __syncthreads();

    const float rx = sp[r * 3 + 0], ry = sp[r * 3 + 1], rz = sp[r * 3 + 2];
    const float r0x = sp0[r * 3 + 0], r0y = sp0[r * 3 + 1], r0z = sp0[r * 3 + 2];

    const float s3 = 1.7320508075688772f, s5 = 2.2360679774997896f,
                s15 = 3.872983346207417f, s35_8 = 2.091650066335189f,
                s105 = 10.246950765959598f, s21_8 = 1.6201851746019651f,
                s7 = 2.6457513110645907f;

    float A[16];
#pragma unroll
    for (int k = 0; k < 16; k++) A[k] = 0.f;

    const float* tb = g_tbl + (size_t)layer * TBL * 512;
    const float* zbase = g_z + b * NN * FF;
    const float* vbase = g_vec + b * NN * 3 * FF;

    for (int s = q; s < NN; s += 4) {
        if (s == r) continue;
        // envelope from ORIGINAL positions (lengths_0)
        float dx0 = r0x - sp0[s * 3 + 0];
        float dy0 = r0y - sp0[s * 3 + 1];
        float dz0 = r0z - sp0[s * 3 + 2];
        float l0 = sqrtf(dx0 * dx0 + dy0 * dy0 + dz0 * dz0 + 1e-12f);
        float env = (l0 < 10.0f) ? 0.5f * (cosf(l0 * 0.3141592653589793f) + 1.0f) : 0.0f;
        if (env == 0.0f) continue;

        float vx = rx - sp[s * 3 + 0];
        float vy = ry - sp[s * 3 + 1];
        float vz = rz - sp[s * 3 + 2];
        float lng = sqrtf(vx * vx + vy * vy + vz * vz + 1e-12f);
        float inv = 1.0f / lng;
        float ux = vx * inv, uy = vy * inv, uz = vz * inv;

        // spherical harmonics (l<=3)
        float xx = ux * ux, yy = uy * uy, zz = uz * uz;
        float Y1 = s3 * ux, Y2 = s3 * uy, Y3 = s3 * uz;
        float Y4 = s15 * ux * uy, Y5 = s15 * uy * uz;
        float Y6 = 0.5f * s5 * (3.f * zz - 1.f);
        float Y7 = s15 * ux * uz;
        float Y8 = 0.5f * s15 * (xx - yy);
        float Y9 = s35_8 * uy * (3.f * xx - yy);
        float Y10 = s105 * ux * uy * uz;
        float Y11 = s21_8 * uy * (5.f * zz - 1.f);
        float Y12 = 0.5f * s7 * uz * (5.f * zz - 3.f);
        float Y13 = s21_8 * ux * (5.f * zz - 1.f);
        float Y14 = 0.5f * s105 * uz * (xx - yy);
        float Y15 = s35_8 * ux * (xx - 3.f * yy);

        // radial weights via table lookup + lerp
        float tp = fminf(lng * TBL_SCALE, (float)TBL - 1.001f);
        int it = (int)tp;
        float fr = tp - (float)it;
        const float4 w0 = *(const float4*)(tb + (size_t)it * 512 + (c << 2));
        const float4 w1 = *(const float4*)(tb + (size_t)(it + 1) * 512 + (c << 2));
        float Rw0 = (w0.x + fr * (w1.x - w0.x)) * env;
        float Rw1 = (w0.y + fr * (w1.y - w0.y)) * env;
        float Rw2 = (w0.z + fr * (w1.z - w0.z)) * env;
        float Rw3 = (w0.w + fr * (w1.w - w0.w)) * env;

        // f = z[s] + vec[s] . u
        const float* vrow = vbase + s * 3 * FF;
        float f = zbase[s * FF + c];
        f = fmaf(vrow[c], ux, f);
        f = fmaf(vrow[FF + c], uy, f);
        f = fmaf(vrow[2 * FF + c], uz, f);

        float t0 = Rw0 * f, t1 = Rw1 * f, t2 = Rw2 * f, t3 = Rw3 * f;
        A[0] += t0;
        A[1]  = fmaf(t1, Y1,  A[1]);
        A[2]  = fmaf(t1, Y2,  A[2]);
        A[3]  = fmaf(t1, Y3,  A[3]);
        A[4]  = fmaf(t2, Y4,  A[4]);
        A[5]  = fmaf(t2, Y5,  A[5]);
        A[6]  = fmaf(t2, Y6,  A[6]);
        A[7]  = fmaf(t2, Y7,  A[7]);
        A[8]  = fmaf(t2, Y8,  A[8]);
        A[9]  = fmaf(t3, Y9,  A[9]);
        A[10] = fmaf(t3, Y10, A[10]);
        A[11] = fmaf(t3, Y11, A[11]);
        A[12] = fmaf(t3, Y12, A[12]);
        A[13] = fmaf(t3, Y13, A[13]);
        A[14] = fmaf(t3, Y14, A[14]);
        A[15] = fmaf(t3, Y15, A[15]);
    }

    // reduce partial A over the 4 sender groups
    if (q > 0) {
#pragma unroll
        for (int k = 0; k < 16; k++) red[q - 1][k * FF + c] = A[k];
    }
    __syncthreads();
    if (q != 0) return;

#pragma unroll
    for (int k = 0; k < 16; k++)
        A[k] = (A[k] + red[0][k * FF + c] + red[1][k * FF + c] + red[2][k * FF + c])
               * (1.0f / 16.0f);

    // per-ell invariants
    float n0 = A[0] * A[0];
    float n1 = A[1] * A[1] + A[2] * A[2] + A[3] * A[3];

    const int co = (layer * 4) * FF + c;
    float g0 = 1.f + c1w[co]      * n0 + c2w[co]      * n0 * n0 + c3w[co]      * n0 * n0 * n0;
    float g1 = 1.f + c1w[co + FF] * n1 + c2w[co + FF] * n1 * n1 + c3w[co + FF] * n1 * n1 * n1;

    float* dst = g_A4 + ((size_t)(b * NN + r)) * 4 * FF;
    dst[c]          = A[0] * g0;
    dst[FF + c]     = A[1] * g1;
    dst[2 * FF + c] = A[2] * g1;
    dst[3 * FF + c] = A[3] * g1;
}

// ---------------- node update: mix, gate, position update, next-layer z ---
__global__ __launch_bounds__(128) void k_node(const float* __restrict__ Wmix0,
                                              const float* __restrict__ Wmix1,
                                              const float* __restrict__ Wg1,
                                              const float* __restrict__ Wg2,
                                              const float* __restrict__ Wvout,
                                              const float* __restrict__ Wnode,
                                              int layer) {
    int bn = blockIdx.x;
    int c = threadIdx.x;
    __shared__ float sA[4 * FF];
    __shared__ float sscal[FF];
    __shared__ float sh[16];
    __shared__ float rb[3][4];

    const float* asrc = g_A4 + (size_t)bn * 4 * FF;
#pragma unroll
    for (int k = 0; k < 4; k++) sA[k * FF + c] = asrc[k * FF + c];
    __syncthreads();

    const float* M0 = Wmix0 + layer * FF * FF;
    const float* M1 = Wmix1 + layer * FF * FF;
    float sc = 0.f, v0 = 0.f, v1 = 0.f, v2 = 0.f;
#pragma unroll 4
    for (int k = 0; k < FF; k++) {
        float m0 = M0[k * FF + c];
        float m1 = M1[k * FF + c];
        sc = fmaf(sA[k],          m0, sc);
        v0 = fmaf(sA[FF + k],     m1, v0);
        v1 = fmaf(sA[2 * FF + k], m1, v1);
        v2 = fmaf(sA[3 * FF + k], m1, v2);
    }
    sscal[c] = sc;
    __syncthreads();

    if (c < 16) {
        const float* G1 = Wg1 + layer * FF * 16;
        float a = 0.f;
#pragma unroll 8
        for (int k = 0; k < FF; k++) a = fmaf(sscal[k], G1[k * 16 + c], a);
        sh[c] = a / (1.0f + expf(-a));
    }
    __syncthreads();

    const float* G2 = Wg2 + layer * 16 * FF;
    float gate = 0.f;
#pragma unroll
    for (int j = 0; j < 16; j++) gate = fmaf(sh[j], G2[j * FF + c], gate);
    float w = gate * Wvout[layer * FF + c];

    float m0 = v0 * w, m1 = v1 * w, m2 = v2 * w;
#pragma unroll
    for (int off = 16; off > 0; off >>= 1) {
        m0 += __shfl_down_sync(0xffffffffu, m0, off);
        m1 += __shfl_down_sync(0xffffffffu, m1, off);
        m2 += __shfl_down_sync(0xffffffffu, m2, off);
    }
    if ((c & 31) == 0) {
        int wp = c >> 5;
        rb[0][wp] = m0; rb[1][wp] = m1; rb[2][wp] = m2;
    }
    __syncthreads();
    if (c < 3) {
        float acc = rb[c][0] + rb[c][1] + rb[c][2] + rb[c][3];
        g_pos[bn * 3 + c] += acc;
    }

    g_scal[bn * FF + c] = sc;
    g_vec[bn * 3 * FF + c] = v0;
    g_vec[bn * 3 * FF + FF + c] = v1;
    g_vec[bn * 3 * FF + 2 * FF + c] = v2;

    // fused z for next layer: z = scal_new @ Wnode[layer+1]
    if (layer + 1 < LL) {
        const float* W = Wnode + (layer + 1) * FF * FF;
        float acc = 0.f;
#pragma unroll 8
        for (int k = 0; k < FF; k++)
            acc = fmaf(sscal[k], W[k * FF + c], acc);
        g_z[bn * FF + c] = acc;
    }
}

// ---------------- output: pos - pos0 ---------------------------------------
__global__ void k_out(const float* __restrict__ pos_in, float* __restrict__ out) {
    int i = blockIdx.x * blockDim.x + threadIdx.x;
    if (i < BB * NN * 3) out[i] = g_pos[i] - pos_in[i];
}

// ---------------------------------------------------------------------------
extern "C" void kernel_launch(void* const* d_in, const int* in_sizes, int n_in,
                              void* d_out, int out_size) {
    const float* positions     = (const float*)d_in[0];
    const int*   node_features = (const int*)d_in[1];
    const float* gf            = (const float*)d_in[2];
    const float* W_embed       = (const float*)d_in[3];
    const float* b_embed       = (const float*)d_in[4];
    const float* Wr1           = (const float*)d_in[5];
    const float* br1           = (const float*)d_in[6];
    const float* Wr2           = (const float*)d_in[7];
    const float* Wnode         = (const float*)d_in[8];
    const float* c1w           = (const float*)d_in[9];
    const float* c2w           = (const float*)d_in[10];
    const float* c3w           = (const float*)d_in[11];
    const float* Wmix0         = (const float*)d_in[12];
    const float* Wmix1         = (const float*)d_in[13];
    const float* Wg1           = (const float*)d_in[14];
    const float* Wg2           = (const float*)d_in[15];
    const float* Wvout         = (const float*)d_in[16];
    float* out = (float*)d_out;

    k_tables<<<dim3(TBL, LL), 128>>>(Wr1, br1, Wr2);
    k_init<<<BB * NN, 128>>>(positions, node_features, gf, W_embed, b_embed, Wnode);
    for (int i = 0; i < LL; i++) {
        k_msg<<<dim3(NN, BB), dim3(128, 4)>>>(positions, c1w, c2w, c3w, i);
        k_node<<<BB * NN, 128>>>(Wmix0, Wmix1, Wg1, Wg2, Wvout, Wnode, i);
    }
    k_out<<<(BB * NN * 3 + 127) / 128, 128>>>(positions, out);
}

// round 3
// speedup vs baseline: 1.3860x; 1.1163x over previous
#include <cuda_runtime.h>
#include <math.h>

#define BB 4
#define NN 128
#define FF 128
#define SS 5
#define TGLOB 32
#define LL 2
#define TBL 512
#define LMAX 16.0f
#define TBL_SCALE (TBL / LMAX)

// ---------------- persistent scratch (device globals; no allocation) ------
__device__ float g_pos[BB * NN * 3];
__device__ float g_scal[BB * NN * FF];
__device__ float g_vec[BB * NN * 3 * FF];   // [b][n][d][c]
__device__ float g_z[BB * NN * FF];
__device__ float g_A4[BB * NN * 4 * FF];    // gated A for k=0..3 only
__device__ float g_tbl[LL * TBL * 512];     // radial MLP table, [layer][t][c*4+j]

// ---------------- table build: Rw(lng) = silu(lng*Wr1+br1) @ Wr2 ----------
__global__ __launch_bounds__(128) void k_tables(const float* __restrict__ Wr1,
                                                const float* __restrict__ br1,
                                                const float* __restrict__ Wr2) {
    int t = blockIdx.x, i = blockIdx.y, c = threadIdx.x;
    float lng = (float)t * (LMAX / (float)TBL);
    __shared__ float h[64];
    if (c < 64) {
        float p = lng * Wr1[i * 64 + c] + br1[i * 64 + c];
        h[c] = p / (1.0f + expf(-p));
    }
    __syncthreads();
    const float* W = Wr2 + i * 64 * 512;
    float a0 = 0.f, a1 = 0.f, a2 = 0.f, a3 = 0.f;
#pragma unroll 8
    for (int m = 0; m < 64; m++) {
        float hm = h[m];
        const float* Wm = W + m * 512 + c;
        a0 = fmaf(hm, Wm[0],   a0);
        a1 = fmaf(hm, Wm[128], a1);
        a2 = fmaf(hm, Wm[256], a2);
        a3 = fmaf(hm, Wm[384], a3);
    }
    float* dst = g_tbl + ((size_t)i * TBL + t) * 512 + c * 4;
    dst[0] = a0; dst[1] = a1; dst[2] = a2; dst[3] = a3;
}

// ---------------- init: embed scalars, zero vectors, z(layer0) ------------
__global__ __launch_bounds__(128) void k_init(const float* __restrict__ positions,
                                              const int* __restrict__ node_features,
                                              const float* __restrict__ gf,
                                              const float* __restrict__ W_embed,
                                              const float* __restrict__ b_embed,
                                              const float* __restrict__ Wnode) {
    int bn = blockIdx.x;           // b*NN + n
    int b = bn / NN;
    int c = threadIdx.x;
    int nf = node_features[bn];    // 1..SS
    float s = W_embed[(nf - 1) * FF + c] + b_embed[c];
#pragma unroll 8
    for (int t = 0; t < TGLOB; t++)
        s = fmaf(gf[b * TGLOB + t], W_embed[(SS + t) * FF + c], s);
    g_scal[bn * FF + c] = s;
    g_vec[bn * 3 * FF + 0 * FF + c] = 0.f;
    g_vec[bn * 3 * FF + 1 * FF + c] = 0.f;
    g_vec[bn * 3 * FF + 2 * FF + c] = 0.f;
    if (c < 3) g_pos[bn * 3 + c] = positions[bn * 3 + c];

    // fused z for layer 0: z = scal @ Wnode[0]
    __shared__ float srow[FF];
    srow[c] = s;
    __syncthreads();
    float acc = 0.f;
#pragma unroll 8
    for (int k = 0; k < FF; k++)
        acc = fmaf(srow[k], Wnode[k * FF + c], acc);
    g_z[bn * FF + c] = acc;
}

// ---------------- message gather + symmetric-contraction gate -------------
// blockDim = (128, 4): c = channel, q = sender-group (senders q, q+4, ...)
__global__ __launch_bounds__(512) void k_msg(const float* __restrict__ pos_in,
                                             const float* __restrict__ c1w,
                                             const float* __restrict__ c2w,
                                             const float* __restrict__ c3w,
                                             int layer) {
    const int r = blockIdx.x;
    const int b = blockIdx.y;
    const int c = threadIdx.x;
    const int q = threadIdx.y;
    const int tid = q * 128 + c;

    __shared__ float sp[NN * 3];
    __shared__ float sp0[NN * 3];
    __shared__ float red[3][16 * FF];
    for (int idx = tid; idx < NN * 3; idx += 512) {
        sp[idx]  = g_pos[b * NN * 3 + idx];
        sp0[idx] = pos_in[b * NN * 3 + idx];
    }
    __syncthreads();

    const float rx = sp[r * 3 + 0], ry = sp[r * 3 + 1], rz = sp[r * 3 + 2];
    const float r0x = sp0[r * 3 + 0], r0y = sp0[r * 3 + 1], r0z = sp0[r * 3 + 2];

    const float s3 = 1.7320508075688772f, s5 = 2.2360679774997896f,
                s15 = 3.872983346207417f, s35_8 = 2.091650066335189f,
                s105 = 10.246950765959598f, s21_8 = 1.6201851746019651f,
                s7 = 2.6457513110645907f;

    float A[16];
#pragma unroll
    for (int k = 0; k < 16; k++) A[k] = 0.f;

    const float* tb = g_tbl + (size_t)layer * TBL * 512;
    const float* zbase = g_z + b * NN * FF;
    const float* vbase = g_vec + b * NN * 3 * FF;

    for (int s = q; s < NN; s += 4) {
        if (s == r) continue;
        float dx0 = r0x - sp0[s * 3 + 0];
        float dy0 = r0y - sp0[s * 3 + 1];
        float dz0 = r0z - sp0[s * 3 + 2];
        float l0 = sqrtf(dx0 * dx0 + dy0 * dy0 + dz0 * dz0 + 1e-12f);
        float env = (l0 < 10.0f) ? 0.5f * (cosf(l0 * 0.3141592653589793f) + 1.0f) : 0.0f;
        if (env == 0.0f) continue;

        float vx = rx - sp[s * 3 + 0];
        float vy = ry - sp[s * 3 + 1];
        float vz = rz - sp[s * 3 + 2];
        float lng = sqrtf(vx * vx + vy * vy + vz * vz + 1e-12f);
        float inv = 1.0f / lng;
        float ux = vx * inv, uy = vy * inv, uz = vz * inv;

        float xx = ux * ux, yy = uy * uy, zz = uz * uz;
        float Y1 = s3 * ux, Y2 = s3 * uy, Y3 = s3 * uz;
        float Y4 = s15 * ux * uy, Y5 = s15 * uy * uz;
        float Y6 = 0.5f * s5 * (3.f * zz - 1.f);
        float Y7 = s15 * ux * uz;
        float Y8 = 0.5f * s15 * (xx - yy);
        float Y9 = s35_8 * uy * (3.f * xx - yy);
        float Y10 = s105 * ux * uy * uz;
        float Y11 = s21_8 * uy * (5.f * zz - 1.f);
        float Y12 = 0.5f * s7 * uz * (5.f * zz - 3.f);
        float Y13 = s21_8 * ux * (5.f * zz - 1.f);
        float Y14 = 0.5f * s105 * uz * (xx - yy);
        float Y15 = s35_8 * ux * (xx - 3.f * yy);

        float tp = fminf(lng * TBL_SCALE, (float)TBL - 1.001f);
        int it = (int)tp;
        float fr = tp - (float)it;
        const float4 w0 = *(const float4*)(tb + (size_t)it * 512 + (c << 2));
        const float4 w1 = *(const float4*)(tb + (size_t)(it + 1) * 512 + (c << 2));
        float Rw0 = (w0.x + fr * (w1.x - w0.x)) * env;
        float Rw1 = (w0.y + fr * (w1.y - w0.y)) * env;
        float Rw2 = (w0.z + fr * (w1.z - w0.z)) * env;
        float Rw3 = (w0.w + fr * (w1.w - w0.w)) * env;

        const float* vrow = vbase + s * 3 * FF;
        float f = zbase[s * FF + c];
        f = fmaf(vrow[c], ux, f);
        f = fmaf(vrow[FF + c], uy, f);
        f = fmaf(vrow[2 * FF + c], uz, f);

        float t0 = Rw0 * f, t1 = Rw1 * f, t2 = Rw2 * f, t3 = Rw3 * f;
        A[0] += t0;
        A[1]  = fmaf(t1, Y1,  A[1]);
        A[2]  = fmaf(t1, Y2,  A[2]);
        A[3]  = fmaf(t1, Y3,  A[3]);
        A[4]  = fmaf(t2, Y4,  A[4]);
        A[5]  = fmaf(t2, Y5,  A[5]);
        A[6]  = fmaf(t2, Y6,  A[6]);
        A[7]  = fmaf(t2, Y7,  A[7]);
        A[8]  = fmaf(t2, Y8,  A[8]);
        A[9]  = fmaf(t3, Y9,  A[9]);
        A[10] = fmaf(t3, Y10, A[10]);
        A[11] = fmaf(t3, Y11, A[11]);
        A[12] = fmaf(t3, Y12, A[12]);
        A[13] = fmaf(t3, Y13, A[13]);
        A[14] = fmaf(t3, Y14, A[14]);
        A[15] = fmaf(t3, Y15, A[15]);
    }

    if (q > 0) {
#pragma unroll
        for (int k = 0; k < 16; k++) red[q - 1][k * FF + c] = A[k];
    }
    __syncthreads();
    if (q != 0) return;

#pragma unroll
    for (int k = 0; k < 16; k++)
        A[k] = (A[k] + red[0][k * FF + c] + red[1][k * FF + c] + red[2][k * FF + c])
               * (1.0f / 16.0f);

    float n0 = A[0] * A[0];
    float n1 = A[1] * A[1] + A[2] * A[2] + A[3] * A[3];

    const int co = (layer * 4) * FF + c;
    float g0 = 1.f + c1w[co]      * n0 + c2w[co]      * n0 * n0 + c3w[co]      * n0 * n0 * n0;
    float g1 = 1.f + c1w[co + FF] * n1 + c2w[co + FF] * n1 * n1 + c3w[co + FF] * n1 * n1 * n1;

    float* dst = g_A4 + ((size_t)(b * NN + r)) * 4 * FF;
    dst[c]          = A[0] * g0;
    dst[FF + c]     = A[1] * g1;
    dst[2 * FF + c] = A[2] * g1;
    dst[3 * FF + c] = A[3] * g1;
}

// ---------------- node update: mix, gate, position update, next-layer z ---
// blockDim = (128, 4): c = output channel, q = k-range [q*32, q*32+32)
__global__ __launch_bounds__(512) void k_node(const float* __restrict__ Wmix0,
                                              const float* __restrict__ Wmix1,
                                              const float* __restrict__ Wg1,
                                              const float* __restrict__ Wg2,
                                              const float* __restrict__ Wvout,
                                              const float* __restrict__ Wnode,
                                              int layer) {
    const int bn = blockIdx.x;
    const int c = threadIdx.x;
    const int q = threadIdx.y;
    const int tid = q * 128 + c;

    __shared__ float sA[4 * FF];
    __shared__ float part[4][4 * FF];
    __shared__ float sscal[FF];
    __shared__ float shp[4][16];
    __shared__ float sh[16];
    __shared__ float rb[3][4];

    const float* asrc = g_A4 + (size_t)bn * 4 * FF;
    for (int idx = tid; idx < 4 * FF; idx += 512) sA[idx] = asrc[idx];
    __syncthreads();

    const float* M0 = Wmix0 + layer * FF * FF;
    const float* M1 = Wmix1 + layer * FF * FF;
    {
        float sc = 0.f, v0 = 0.f, v1 = 0.f, v2 = 0.f;
#pragma unroll
        for (int kk = 0; kk < 32; kk++) {
            int k = q * 32 + kk;
            float m0 = M0[k * FF + c];
            float m1 = M1[k * FF + c];
            sc = fmaf(sA[k],          m0, sc);
            v0 = fmaf(sA[FF + k],     m1, v0);
            v1 = fmaf(sA[2 * FF + k], m1, v1);
            v2 = fmaf(sA[3 * FF + k], m1, v2);
        }
        part[q][c]          = sc;
        part[q][FF + c]     = v0;
        part[q][2 * FF + c] = v1;
        part[q][3 * FF + c] = v2;
    }
    __syncthreads();

    float sc = part[0][c] + part[1][c] + part[2][c] + part[3][c];
    float v0 = part[0][FF + c] + part[1][FF + c] + part[2][FF + c] + part[3][FF + c];
    float v1 = part[0][2*FF + c] + part[1][2*FF + c] + part[2][2*FF + c] + part[3][2*FF + c];
    float v2 = part[0][3*FF + c] + part[1][3*FF + c] + part[2][3*FF + c] + part[3][3*FF + c];
    if (q == 0) sscal[c] = sc;
    __syncthreads();

    // Wg1 GEMV (128->16), split over q
    if (c < 16) {
        const float* G1 = Wg1 + layer * FF * 16;
        float a = 0.f;
#pragma unroll
        for (int kk = 0; kk < 32; kk++) {
            int k = q * 32 + kk;
            a = fmaf(sscal[k], G1[k * 16 + c], a);
        }
        shp[q][c] = a;
    }
    __syncthreads();
    if (q == 0 && c < 16) {
        float a = shp[0][c] + shp[1][c] + shp[2][c] + shp[3][c];
        sh[c] = a / (1.0f + expf(-a));
    }
    __syncthreads();

    // gate + position update (q==0 group only does the reduction)
    if (q == 0) {
        const float* G2 = Wg2 + layer * 16 * FF;
        float gate = 0.f;
#pragma unroll
        for (int j = 0; j < 16; j++) gate = fmaf(sh[j], G2[j * FF + c], gate);
        float w = gate * Wvout[layer * FF + c];

        float m0 = v0 * w, m1 = v1 * w, m2 = v2 * w;
#pragma unroll
        for (int off = 16; off > 0; off >>= 1) {
            m0 += __shfl_down_sync(0xffffffffu, m0, off);
            m1 += __shfl_down_sync(0xffffffffu, m1, off);
            m2 += __shfl_down_sync(0xffffffffu, m2, off);
        }
        if ((c & 31) == 0) {
            int wp = c >> 5;
            rb[0][wp] = m0; rb[1][wp] = m1; rb[2][wp] = m2;
        }
    }
    __syncthreads();
    if (q == 0) {
        if (c < 3) {
            float acc = rb[c][0] + rb[c][1] + rb[c][2] + rb[c][3];
            g_pos[bn * 3 + c] += acc;
        }
        g_scal[bn * FF + c] = sc;
        g_vec[bn * 3 * FF + c] = v0;
        g_vec[bn * 3 * FF + FF + c] = v1;
        g_vec[bn * 3 * FF + 2 * FF + c] = v2;
    }

    // fused z for next layer: z = scal_new @ Wnode[layer+1], split over q
    if (layer + 1 < LL) {
        const float* W = Wnode + (layer + 1) * FF * FF;
        float acc = 0.f;
#pragma unroll
        for (int kk = 0; kk < 32; kk++) {
            int k = q * 32 + kk;
            acc = fmaf(sscal[k], W[k * FF + c], acc);
        }
        part[q][c] = acc;
        __syncthreads();
        if (q == 0)
            g_z[bn * FF + c] = part[0][c] + part[1][c] + part[2][c] + part[3][c];
    }
}

// ---------------- output: pos - pos0 ---------------------------------------
__global__ void k_out(const float* __restrict__ pos_in, float* __restrict__ out) {
    int i = blockIdx.x * blockDim.x + threadIdx.x;
    if (i < BB * NN * 3) out[i] = g_pos[i] - pos_in[i];
}

// ---------------------------------------------------------------------------
extern "C" void kernel_launch(void* const* d_in, const int* in_sizes, int n_in,
                              void* d_out, int out_size) {
    const float* positions     = (const float*)d_in[0];
    const int*   node_features = (const int*)d_in[1];
    const float* gf            = (const float*)d_in[2];
    const float* W_embed       = (const float*)d_in[3];
    const float* b_embed       = (const float*)d_in[4];
    const float* Wr1           = (const float*)d_in[5];
    const float* br1           = (const float*)d_in[6];
    const float* Wr2           = (const float*)d_in[7];
    const float* Wnode         = (const float*)d_in[8];
    const float* c1w           = (const float*)d_in[9];
    const float* c2w           = (const float*)d_in[10];
    const float* c3w           = (const float*)d_in[11];
    const float* Wmix0         = (const float*)d_in[12];
    const float* Wmix1         = (const float*)d_in[13];
    const float* Wg1           = (const float*)d_in[14];
    const float* Wg2           = (const float*)d_in[15];
    const float* Wvout         = (const float*)d_in[16];
    float* out = (float*)d_out;

    k_tables<<<dim3(TBL, LL), 128>>>(Wr1, br1, Wr2);
    k_init<<<BB * NN, 128>>>(positions, node_features, gf, W_embed, b_embed, Wnode);
    for (int i = 0; i < LL; i++) {
        k_msg<<<dim3(NN, BB), dim3(128, 4)>>>(positions, c1w, c2w, c3w, i);
        k_node<<<BB * NN, dim3(128, 4)>>>(Wmix0, Wmix1, Wg1, Wg2, Wvout, Wnode, i);
    }
    k_out<<<(BB * NN * 3 + 127) / 128, 128>>>(positions, out);
}